// round 1
// baseline (speedup 1.0000x reference)
#include <cuda_runtime.h>
#include <math_constants.h>

#define NHEAD 16
#define HDIM  64
#define SEQ   2048
#define BATCH 2
#define CDIM  1024
#define MROWS (BATCH*SEQ)   // 4096

// ---------------- scratch (static device memory; no runtime allocation) ----------------
__device__ float g_qkv[(size_t)MROWS * 3 * CDIM];          // 48 MB
__device__ float g_Q[(size_t)BATCH*NHEAD*SEQ*HDIM];        // 16 MB
__device__ float g_K[(size_t)BATCH*NHEAD*SEQ*HDIM];
__device__ float g_V[(size_t)BATCH*NHEAD*SEQ*HDIM];
__device__ float g_y[(size_t)MROWS*CDIM];                  // 16 MB
__device__ float g_cos[SEQ*HDIM];
__device__ float g_sin[SEQ*HDIM];

// ---------------- RoPE cos/sin cache ----------------
__global__ void rope_cache_kernel() {
  int idx = blockIdx.x*blockDim.x + threadIdx.x;
  if (idx >= SEQ*HDIM) return;
  int t = idx >> 6;
  int d = idx & 63;
  int j = d & 31;                      // freq index = d mod 32 (concat([freqs,freqs]))
  float inv = powf(10000.0f, -(float)j / 32.0f);
  float ang = (float)t * inv;
  float s, c;
  sincosf(ang, &s, &c);
  g_cos[idx] = c;
  g_sin[idx] = s;
}

// ---------------- SGEMM: C[M,N] = A[M,K] * B[N,K]^T (both row-major, K contiguous) ----------------
__global__ __launch_bounds__(256, 2)
void sgemm_nt(const float* __restrict__ A, const float* __restrict__ B,
              float* __restrict__ C, int M, int N, int K) {
  __shared__ float As[8][132];   // +4 pad: conflict-free transposed stores, aligned f4 reads
  __shared__ float Bs[8][132];
  const int tid = threadIdx.x;
  const int tx = tid & 15, ty = tid >> 4;
  const int lr = tid >> 1, lc = (tid & 1) << 2;
  const float* Ap = A + (size_t)(blockIdx.y*128 + lr)*K + lc;
  const float* Bp = B + (size_t)(blockIdx.x*128 + lr)*K + lc;
  float acc[8][8];
#pragma unroll
  for (int i = 0; i < 8; i++)
#pragma unroll
    for (int j = 0; j < 8; j++) acc[i][j] = 0.f;

  for (int k0 = 0; k0 < K; k0 += 8) {
    float4 av = *(const float4*)(Ap + k0);
    float4 bv = *(const float4*)(Bp + k0);
    __syncthreads();
    As[lc+0][lr] = av.x; As[lc+1][lr] = av.y; As[lc+2][lr] = av.z; As[lc+3][lr] = av.w;
    Bs[lc+0][lr] = bv.x; Bs[lc+1][lr] = bv.y; Bs[lc+2][lr] = bv.z; Bs[lc+3][lr] = bv.w;
    __syncthreads();
#pragma unroll
    for (int kk = 0; kk < 8; kk++) {
      float a[8], b[8];
      *(float4*)&a[0] = *(const float4*)&As[kk][ty*8];
      *(float4*)&a[4] = *(const float4*)&As[kk][ty*8+4];
      *(float4*)&b[0] = *(const float4*)&Bs[kk][tx*8];
      *(float4*)&b[4] = *(const float4*)&Bs[kk][tx*8+4];
#pragma unroll
      for (int i = 0; i < 8; i++)
#pragma unroll
        for (int j = 0; j < 8; j++)
          acc[i][j] = fmaf(a[i], b[j], acc[i][j]);
    }
  }
  const int crow = blockIdx.y*128 + ty*8;
  const int ccol = blockIdx.x*128 + tx*8;
#pragma unroll
  for (int i = 0; i < 8; i++) {
    *(float4*)&C[(size_t)(crow+i)*N + ccol]   = make_float4(acc[i][0],acc[i][1],acc[i][2],acc[i][3]);
    *(float4*)&C[(size_t)(crow+i)*N + ccol+4] = make_float4(acc[i][4],acc[i][5],acc[i][6],acc[i][7]);
  }
}

// ---------------- RoPE apply + head-major reshape ----------------
// qkv[m, 0:1024]=q, [1024:2048]=k, [2048:3072]=v  ->  Q/K/V in [b,h,t,d]
// rotate_half (interleaved): out[2i] = q[2i]*cos[2i] - q[2i+1]*sin[2i]
//                            out[2i+1] = q[2i+1]*cos[2i+1] + q[2i]*sin[2i+1]
__global__ void rope_apply_kernel() {
  int p = blockIdx.x*blockDim.x + threadIdx.x;   // pair index
  if (p >= MROWS*1536) return;
  int m   = p / 1536;
  int col = (p % 1536) * 2;
  int b = m >> 11;
  int t = m & 2047;
  int sec = col >> 10;         // 0=q,1=k,2=v
  int cc  = col & 1023;
  int h = cc >> 6;
  int d = cc & 63;
  float2 v = *(const float2*)&g_qkv[(size_t)m*3072 + col];
  float r0, r1;
  if (sec < 2) {
    float c0 = g_cos[t*64 + d],     s0 = g_sin[t*64 + d];
    float c1 = g_cos[t*64 + d + 1], s1 = g_sin[t*64 + d + 1];
    r0 = v.x*c0 - v.y*s0;
    r1 = v.y*c1 + v.x*s1;
  } else { r0 = v.x; r1 = v.y; }
  float* dst = (sec == 0) ? g_Q : (sec == 1) ? g_K : g_V;
  size_t o = ((size_t)((b*NHEAD + h)*SEQ + t))*HDIM + d;
  *(float2*)&dst[o] = make_float2(r0, r1);
}

// ---------------- fp32 flash attention ----------------
// Block: 128 queries x (stream 128-key tiles) for one (b,h). 256 threads.
// Qst/Kst staged d-major (transposed) for SGEMM-style conflict-free f4 reads.
#define QST_LD 132
#define VS_LD  68
#define PS_LD  132
#define ATT_SMEM_FLOATS (64*QST_LD + 64*QST_LD + 128*VS_LD + 128*PS_LD)   // 42496
#define ATT_SMEM_BYTES  (ATT_SMEM_FLOATS*4)                               // 169984

__global__ __launch_bounds__(256, 1)
void flash_attn_kernel() {
  extern __shared__ float sm[];
  float* Qst = sm;                   // [64][132]  (d-major, cols = 128 q rows)
  float* Kst = Qst + 64*QST_LD;      // [64][132]  (d-major, cols = 128 keys)
  float* Vs  = Kst + 64*QST_LD;      // [128][68]  (key-major)
  float* Ps  = Vs  + 128*VS_LD;      // [128][132] (q-major probs)
  const int tid = threadIdx.x;
  const int tx = tid & 15, ty = tid >> 4;
  const int q0 = blockIdx.x * 128;
  const int bh = blockIdx.y;
  const float* Qb = g_Q + (size_t)bh*SEQ*HDIM;
  const float* Kb = g_K + (size_t)bh*SEQ*HDIM;
  const float* Vb = g_V + (size_t)bh*SEQ*HDIM;

  // stage Q transposed, pre-scaled by 1/sqrt(64)
  {
    int r = tid & 127, d0 = (tid >> 7) * 4;
#pragma unroll
    for (int it = 0; it < 8; it++) {
      int d = d0 + it*8;
      float4 v = *(const float4*)(Qb + (size_t)(q0 + r)*64 + d);
      Qst[(d+0)*QST_LD + r] = v.x * 0.125f;
      Qst[(d+1)*QST_LD + r] = v.y * 0.125f;
      Qst[(d+2)*QST_LD + r] = v.z * 0.125f;
      Qst[(d+3)*QST_LD + r] = v.w * 0.125f;
    }
  }

  float m_i[8], l_i[8], o[8][4];
#pragma unroll
  for (int i = 0; i < 8; i++) {
    m_i[i] = -CUDART_INF_F; l_i[i] = 0.f;
#pragma unroll
    for (int j = 0; j < 4; j++) o[i][j] = 0.f;
  }

  for (int kt = 0; kt < SEQ/128; kt++) {
    __syncthreads();   // previous PV done before overwriting K/V tiles
    {
      int c = tid & 127, d0 = (tid >> 7) * 4;
#pragma unroll
      for (int it = 0; it < 8; it++) {
        int d = d0 + it*8;
        float4 v = *(const float4*)(Kb + (size_t)(kt*128 + c)*64 + d);
        Kst[(d+0)*QST_LD + c] = v.x;
        Kst[(d+1)*QST_LD + c] = v.y;
        Kst[(d+2)*QST_LD + c] = v.z;
        Kst[(d+3)*QST_LD + c] = v.w;
      }
#pragma unroll
      for (int it = 0; it < 8; it++) {
        int idx = tid + it*256;
        int cv = idx >> 4, dc = (idx & 15) * 4;
        *(float4*)&Vs[cv*VS_LD + dc] = *(const float4*)(Vb + (size_t)(kt*128 + cv)*64 + dc);
      }
    }
    __syncthreads();

    // S = (Q*scale) @ K^T  : 8x8 frag per thread
    float s[8][8];
#pragma unroll
    for (int i = 0; i < 8; i++)
#pragma unroll
      for (int j = 0; j < 8; j++) s[i][j] = 0.f;
#pragma unroll 8
    for (int dd = 0; dd < 64; dd++) {
      float a[8], bq[8];
      *(float4*)&a[0]  = *(const float4*)&Qst[dd*QST_LD + ty*8];
      *(float4*)&a[4]  = *(const float4*)&Qst[dd*QST_LD + ty*8 + 4];
      *(float4*)&bq[0] = *(const float4*)&Kst[dd*QST_LD + tx*8];
      *(float4*)&bq[4] = *(const float4*)&Kst[dd*QST_LD + tx*8 + 4];
#pragma unroll
      for (int i = 0; i < 8; i++)
#pragma unroll
        for (int j = 0; j < 8; j++)
          s[i][j] = fmaf(a[i], bq[j], s[i][j]);
    }

    // online softmax (row reductions across the 16 tx lanes)
#pragma unroll
    for (int i = 0; i < 8; i++) {
      float mx = s[i][0];
#pragma unroll
      for (int j = 1; j < 8; j++) mx = fmaxf(mx, s[i][j]);
      mx = fmaxf(mx, __shfl_xor_sync(0xffffffffu, mx, 1));
      mx = fmaxf(mx, __shfl_xor_sync(0xffffffffu, mx, 2));
      mx = fmaxf(mx, __shfl_xor_sync(0xffffffffu, mx, 4));
      mx = fmaxf(mx, __shfl_xor_sync(0xffffffffu, mx, 8));
      float m_new = fmaxf(m_i[i], mx);
      float alpha = __expf(m_i[i] - m_new);   // exp(-inf)=0 on first tile
      float rs = 0.f;
#pragma unroll
      for (int j = 0; j < 8; j++) { float pj = __expf(s[i][j] - m_new); s[i][j] = pj; rs += pj; }
      rs += __shfl_xor_sync(0xffffffffu, rs, 1);
      rs += __shfl_xor_sync(0xffffffffu, rs, 2);
      rs += __shfl_xor_sync(0xffffffffu, rs, 4);
      rs += __shfl_xor_sync(0xffffffffu, rs, 8);
      l_i[i] = l_i[i]*alpha + rs;
      m_i[i] = m_new;
#pragma unroll
      for (int j = 0; j < 4; j++) o[i][j] *= alpha;
      *(float4*)&Ps[(ty*8+i)*PS_LD + tx*8]     = make_float4(s[i][0], s[i][1], s[i][2], s[i][3]);
      *(float4*)&Ps[(ty*8+i)*PS_LD + tx*8 + 4] = make_float4(s[i][4], s[i][5], s[i][6], s[i][7]);
    }
    __syncthreads();

    // O += P @ V  : 8x4 frag per thread (cols = head dim tx*4)
#pragma unroll 4
    for (int cc = 0; cc < 128; cc += 4) {
      float pv[8][4];
#pragma unroll
      for (int i = 0; i < 8; i++)
        *(float4*)&pv[i][0] = *(const float4*)&Ps[(ty*8+i)*PS_LD + cc];
      float vv[4][4];
#pragma unroll
      for (int mq = 0; mq < 4; mq++)
        *(float4*)&vv[mq][0] = *(const float4*)&Vs[(cc+mq)*VS_LD + tx*4];
#pragma unroll
      for (int i = 0; i < 8; i++)
#pragma unroll
        for (int mq = 0; mq < 4; mq++)
#pragma unroll
          for (int j = 0; j < 4; j++)
            o[i][j] = fmaf(pv[i][mq], vv[mq][j], o[i][j]);
    }
  }

  // write y in [b, t, h*64+d] layout (ready for the output GEMM)
  const int b = bh >> 4, h = bh & 15;
#pragma unroll
  for (int i = 0; i < 8; i++) {
    int row = q0 + ty*8 + i;
    float inv = 1.0f / l_i[i];
    size_t off = ((size_t)(b*SEQ + row))*CDIM + h*HDIM + tx*4;
    *(float4*)&g_y[off] = make_float4(o[i][0]*inv, o[i][1]*inv, o[i][2]*inv, o[i][3]*inv);
  }
}

// ---------------- launch ----------------
extern "C" void kernel_launch(void* const* d_in, const int* in_sizes, int n_in,
                              void* d_out, int out_size) {
  const float* x    = (const float*)d_in[0];   // (2,2048,1024)
  const float* Wqkv = (const float*)d_in[1];   // (3072,1024)
  const float* Wout = (const float*)d_in[2];   // (1024,1024)
  float* out = (float*)d_out;                  // (2,2048,1024)

  float *qkv = nullptr, *y = nullptr;
  cudaGetSymbolAddress((void**)&qkv, g_qkv);
  cudaGetSymbolAddress((void**)&y,   g_y);

  cudaFuncSetAttribute(flash_attn_kernel,
                       cudaFuncAttributeMaxDynamicSharedMemorySize, ATT_SMEM_BYTES);

  rope_cache_kernel<<<(SEQ*HDIM + 255)/256, 256>>>();
  sgemm_nt<<<dim3(3*CDIM/128, MROWS/128), 256>>>(x, Wqkv, qkv, MROWS, 3*CDIM, CDIM);
  rope_apply_kernel<<<(MROWS*1536 + 255)/256, 256>>>();
  flash_attn_kernel<<<dim3(SEQ/128, BATCH*NHEAD), 256, ATT_SMEM_BYTES>>>();
  sgemm_nt<<<dim3(CDIM/128, MROWS/128), 256>>>(y, Wout, out, MROWS, CDIM, CDIM);
}

// round 5
// speedup vs baseline: 1.3995x; 1.3995x over previous
#include <cuda_runtime.h>
#include <cuda_bf16.h>
#include <math_constants.h>
#include <cstdint>

#define NHEAD 16
#define HDIM  64
#define SEQ   2048
#define BATCH 2
#define CDIM  1024
#define MROWS (BATCH*SEQ)   // 4096

// ---------------- scratch (static device memory; no runtime allocation) ----------------
__device__ float g_qkv[(size_t)MROWS * 3 * CDIM];
__device__ float g_Q[(size_t)BATCH*NHEAD*SEQ*HDIM];
__device__ float g_K[(size_t)BATCH*NHEAD*SEQ*HDIM];
__device__ float g_V[(size_t)BATCH*NHEAD*SEQ*HDIM];
__device__ float g_y[(size_t)MROWS*CDIM];
__device__ float g_cos[SEQ*HDIM];
__device__ float g_sin[SEQ*HDIM];
// bf16 split staging (A reused for x then y; B for Wqkv then Wout)
__device__ __align__(256) __nv_bfloat16 g_Ahi[(size_t)MROWS*CDIM];
__device__ __align__(256) __nv_bfloat16 g_Alo[(size_t)MROWS*CDIM];
__device__ __align__(256) __nv_bfloat16 g_Bhi[(size_t)3*CDIM*CDIM];
__device__ __align__(256) __nv_bfloat16 g_Blo[(size_t)3*CDIM*CDIM];

static __device__ __forceinline__ uint32_t smem_u32(const void* p) {
  uint32_t a;
  asm("{ .reg .u64 t; cvta.to.shared.u64 t, %1; cvt.u32.u64 %0, t; }" : "=r"(a) : "l"(p));
  return a;
}

// ---------------- RoPE cos/sin cache ----------------
__global__ void rope_cache_kernel() {
  int idx = blockIdx.x*blockDim.x + threadIdx.x;
  if (idx >= SEQ*HDIM) return;
  int t = idx >> 6;
  int d = idx & 63;
  int j = d & 31;
  float inv = powf(10000.0f, -(float)j / 32.0f);
  float ang = (float)t * inv;
  float s, c;
  sincosf(ang, &s, &c);
  g_cos[idx] = c;
  g_sin[idx] = s;
}

// ---------------- fp32 -> bf16 hi/lo split ----------------
__global__ void conv_split_kernel(const float* __restrict__ src,
                                  __nv_bfloat16* __restrict__ hi,
                                  __nv_bfloat16* __restrict__ lo, int n) {
  int i = (blockIdx.x*blockDim.x + threadIdx.x) * 4;
  if (i >= n) return;
  float4 v = *(const float4*)(src + i);
  __nv_bfloat16 h0 = __float2bfloat16(v.x);
  __nv_bfloat16 h1 = __float2bfloat16(v.y);
  __nv_bfloat16 h2 = __float2bfloat16(v.z);
  __nv_bfloat16 h3 = __float2bfloat16(v.w);
  __nv_bfloat16 l0 = __float2bfloat16(v.x - __bfloat162float(h0));
  __nv_bfloat16 l1 = __float2bfloat16(v.y - __bfloat162float(h1));
  __nv_bfloat16 l2 = __float2bfloat16(v.z - __bfloat162float(h2));
  __nv_bfloat16 l3 = __float2bfloat16(v.w - __bfloat162float(h3));
  __nv_bfloat162* hp = (__nv_bfloat162*)(hi + i);
  __nv_bfloat162* lp = (__nv_bfloat162*)(lo + i);
  hp[0] = __nv_bfloat162(h0, h1); hp[1] = __nv_bfloat162(h2, h3);
  lp[0] = __nv_bfloat162(l0, l1); lp[1] = __nv_bfloat162(l2, l3);
}

// ================= 3xBF16 mma.sync GEMM: C[M,N] = A[M,K] * B[N,K]^T =================
// CTA 128x128, k-tile 32, double-buffered cp.async. 8 warps (4m x 2n), warp tile 32x64.
// smem row pitch = 40 bf16 (80B) -> ldmatrix phases hit all 32 banks once.
#define GP 40
#define COMP_BYTES (128*GP*2)        // 10240
#define STAGE_BYTES (4*COMP_BYTES)   // 40960
#define GSM_TOTAL (2*STAGE_BYTES)    // 81920

#define LDSM4(R0,R1,R2,R3,ADDR) \
  asm volatile("ldmatrix.sync.aligned.m8n8.x4.shared.b16 {%0,%1,%2,%3}, [%4];" \
    : "=r"(R0),"=r"(R1),"=r"(R2),"=r"(R3) : "r"(ADDR))

#define MMA16816(D,A,B) \
  asm volatile("mma.sync.aligned.m16n8k16.row.col.f32.bf16.bf16.f32 " \
    "{%0,%1,%2,%3}, {%4,%5,%6,%7}, {%8,%9}, {%0,%1,%2,%3};" \
    : "+f"((D)[0]),"+f"((D)[1]),"+f"((D)[2]),"+f"((D)[3]) \
    : "r"((A)[0]),"r"((A)[1]),"r"((A)[2]),"r"((A)[3]), "r"((B)[0]),"r"((B)[1]))

__global__ __launch_bounds__(256, 2)
void gemm_bf16x3(const __nv_bfloat16* __restrict__ Ahi, const __nv_bfloat16* __restrict__ Alo,
                 const __nv_bfloat16* __restrict__ Bhi, const __nv_bfloat16* __restrict__ Blo,
                 float* __restrict__ C, int M, int N, int K) {
  extern __shared__ char sm[];
  const uint32_t sb = smem_u32(sm);
  const int tid = threadIdx.x, warp = tid >> 5, lane = tid & 31;
  const int m0 = blockIdx.y * 128, n0 = blockIdx.x * 128;
  const int warp_m = (warp >> 1) * 32, warp_n = (warp & 1) * 64;

  float acc[2][8][4];
#pragma unroll
  for (int f = 0; f < 2; f++)
#pragma unroll
    for (int t = 0; t < 8; t++)
#pragma unroll
      for (int j = 0; j < 4; j++) acc[f][t][j] = 0.f;

  // cp.async task map: 8 chunks/thread/stage. comp: 0=Ahi 1=Alo 2=Bhi 3=Blo
  const __nv_bfloat16* srcs[4] = {Ahi, Alo, Bhi, Blo};

  auto load_stage = [&](int stage, int k0) {
#pragma unroll
    for (int i = 0; i < 8; i++) {
      int t = tid + i * 256;
      int comp = t >> 9, row = (t >> 2) & 127, ch = t & 3;
      const __nv_bfloat16* src = srcs[comp] +
        (size_t)((comp < 2 ? m0 : n0) + row) * K + k0 + ch * 8;
      uint32_t dst = sb + stage * STAGE_BYTES + comp * COMP_BYTES + row * (GP*2) + ch * 16;
      asm volatile("cp.async.cg.shared.global [%0], [%1], 16;" :: "r"(dst), "l"(src) : "memory");
    }
    asm volatile("cp.async.commit_group;" ::: "memory");
  };

  const int NIT = K / 32;
  load_stage(0, 0);

  for (int kt = 0; kt < NIT; kt++) {
    if (kt + 1 < NIT) {
      load_stage((kt + 1) & 1, (kt + 1) * 32);
      asm volatile("cp.async.wait_group 1;" ::: "memory");
    } else {
      asm volatile("cp.async.wait_group 0;" ::: "memory");
    }
    __syncthreads();

    const uint32_t base = sb + (kt & 1) * STAGE_BYTES;
#pragma unroll
    for (int ks = 0; ks < 2; ks++) {
      // A fragments (hi, lo) for 2 m16 tiles
      uint32_t ah[2][4], al[2][4];
      {
        int arow = (lane & 7) + ((lane >> 3) & 1) * 8;
        int akof = ks * 16 + ((lane >> 4) & 1) * 8;
#pragma unroll
        for (int f = 0; f < 2; f++) {
          uint32_t ao = base + (warp_m + f * 16 + arow) * (GP*2) + akof * 2;
          LDSM4(ah[f][0], ah[f][1], ah[f][2], ah[f][3], ao);
          LDSM4(al[f][0], al[f][1], al[f][2], al[f][3], ao + COMP_BYTES);
        }
      }
      // B: 4 pairs of n8 tiles
      int brow = (lane & 7) + ((lane >> 4) & 1) * 8;
      int bkof = ks * 16 + ((lane >> 3) & 1) * 8;
#pragma unroll
      for (int p = 0; p < 4; p++) {
        uint32_t bo = base + 2 * COMP_BYTES + (warp_n + p * 16 + brow) * (GP*2) + bkof * 2;
        uint32_t bh[4], bl[4];
        LDSM4(bh[0], bh[1], bh[2], bh[3], bo);
        LDSM4(bl[0], bl[1], bl[2], bl[3], bo + COMP_BYTES);
#pragma unroll
        for (int half = 0; half < 2; half++) {
          int t = p * 2 + half;
          uint32_t* bhp = bh + half * 2;
          uint32_t* blp = bl + half * 2;
#pragma unroll
          for (int f = 0; f < 2; f++) {
            MMA16816(acc[f][t], ah[f], bhp);   // hi*hi
            MMA16816(acc[f][t], ah[f], blp);   // hi*lo
            MMA16816(acc[f][t], al[f], bhp);   // lo*hi
          }
        }
      }
    }
    __syncthreads();
  }

  // epilogue
  const int g = lane >> 2, tig = lane & 3;
#pragma unroll
  for (int f = 0; f < 2; f++) {
#pragma unroll
    for (int t = 0; t < 8; t++) {
      int row = m0 + warp_m + f * 16 + g;
      int col = n0 + warp_n + t * 8 + tig * 2;
      *(float2*)&C[(size_t)row * N + col]       = make_float2(acc[f][t][0], acc[f][t][1]);
      *(float2*)&C[(size_t)(row + 8) * N + col] = make_float2(acc[f][t][2], acc[f][t][3]);
    }
  }
}

// ---------------- RoPE apply + head-major reshape ----------------
__global__ void rope_apply_kernel() {
  int p = blockIdx.x*blockDim.x + threadIdx.x;
  if (p >= MROWS*1536) return;
  int m   = p / 1536;
  int col = (p % 1536) * 2;
  int b = m >> 11;
  int t = m & 2047;
  int sec = col >> 10;
  int cc  = col & 1023;
  int h = cc >> 6;
  int d = cc & 63;
  float2 v = *(const float2*)&g_qkv[(size_t)m*3072 + col];
  float r0, r1;
  if (sec < 2) {
    float c0 = g_cos[t*64 + d],     s0 = g_sin[t*64 + d];
    float c1 = g_cos[t*64 + d + 1], s1 = g_sin[t*64 + d + 1];
    r0 = v.x*c0 - v.y*s0;
    r1 = v.y*c1 + v.x*s1;
  } else { r0 = v.x; r1 = v.y; }
  float* dst = (sec == 0) ? g_Q : (sec == 1) ? g_K : g_V;
  size_t o = ((size_t)((b*NHEAD + h)*SEQ + t))*HDIM + d;
  *(float2*)&dst[o] = make_float2(r0, r1);
}

// ---------------- fp32 flash attention (unchanged, passing) ----------------
#define QST_LD 132
#define VS_LD  68
#define PS_LD  132
#define ATT_SMEM_FLOATS (64*QST_LD + 64*QST_LD + 128*VS_LD + 128*PS_LD)
#define ATT_SMEM_BYTES  (ATT_SMEM_FLOATS*4)

__global__ __launch_bounds__(256, 1)
void flash_attn_kernel() {
  extern __shared__ float smf[];
  float* Qst = smf;
  float* Kst = Qst + 64*QST_LD;
  float* Vs  = Kst + 64*QST_LD;
  float* Ps  = Vs  + 128*VS_LD;
  const int tid = threadIdx.x;
  const int tx = tid & 15, ty = tid >> 4;
  const int q0 = blockIdx.x * 128;
  const int bh = blockIdx.y;
  const float* Qb = g_Q + (size_t)bh*SEQ*HDIM;
  const float* Kb = g_K + (size_t)bh*SEQ*HDIM;
  const float* Vb = g_V + (size_t)bh*SEQ*HDIM;

  {
    int r = tid & 127, d0 = (tid >> 7) * 4;
#pragma unroll
    for (int it = 0; it < 8; it++) {
      int d = d0 + it*8;
      float4 v = *(const float4*)(Qb + (size_t)(q0 + r)*64 + d);
      Qst[(d+0)*QST_LD + r] = v.x * 0.125f;
      Qst[(d+1)*QST_LD + r] = v.y * 0.125f;
      Qst[(d+2)*QST_LD + r] = v.z * 0.125f;
      Qst[(d+3)*QST_LD + r] = v.w * 0.125f;
    }
  }

  float m_i[8], l_i[8], o[8][4];
#pragma unroll
  for (int i = 0; i < 8; i++) {
    m_i[i] = -CUDART_INF_F; l_i[i] = 0.f;
#pragma unroll
    for (int j = 0; j < 4; j++) o[i][j] = 0.f;
  }

  for (int kt = 0; kt < SEQ/128; kt++) {
    __syncthreads();
    {
      int c = tid & 127, d0 = (tid >> 7) * 4;
#pragma unroll
      for (int it = 0; it < 8; it++) {
        int d = d0 + it*8;
        float4 v = *(const float4*)(Kb + (size_t)(kt*128 + c)*64 + d);
        Kst[(d+0)*QST_LD + c] = v.x;
        Kst[(d+1)*QST_LD + c] = v.y;
        Kst[(d+2)*QST_LD + c] = v.z;
        Kst[(d+3)*QST_LD + c] = v.w;
      }
#pragma unroll
      for (int it = 0; it < 8; it++) {
        int idx = tid + it*256;
        int cv = idx >> 4, dc = (idx & 15) * 4;
        *(float4*)&Vs[cv*VS_LD + dc] = *(const float4*)(Vb + (size_t)(kt*128 + cv)*64 + dc);
      }
    }
    __syncthreads();

    float s[8][8];
#pragma unroll
    for (int i = 0; i < 8; i++)
#pragma unroll
      for (int j = 0; j < 8; j++) s[i][j] = 0.f;
#pragma unroll 8
    for (int dd = 0; dd < 64; dd++) {
      float a[8], bq[8];
      *(float4*)&a[0]  = *(const float4*)&Qst[dd*QST_LD + ty*8];
      *(float4*)&a[4]  = *(const float4*)&Qst[dd*QST_LD + ty*8 + 4];
      *(float4*)&bq[0] = *(const float4*)&Kst[dd*QST_LD + tx*8];
      *(float4*)&bq[4] = *(const float4*)&Kst[dd*QST_LD + tx*8 + 4];
#pragma unroll
      for (int i = 0; i < 8; i++)
#pragma unroll
        for (int j = 0; j < 8; j++)
          s[i][j] = fmaf(a[i], bq[j], s[i][j]);
    }

#pragma unroll
    for (int i = 0; i < 8; i++) {
      float mx = s[i][0];
#pragma unroll
      for (int j = 1; j < 8; j++) mx = fmaxf(mx, s[i][j]);
      mx = fmaxf(mx, __shfl_xor_sync(0xffffffffu, mx, 1));
      mx = fmaxf(mx, __shfl_xor_sync(0xffffffffu, mx, 2));
      mx = fmaxf(mx, __shfl_xor_sync(0xffffffffu, mx, 4));
      mx = fmaxf(mx, __shfl_xor_sync(0xffffffffu, mx, 8));
      float m_new = fmaxf(m_i[i], mx);
      float alpha = __expf(m_i[i] - m_new);
      float rs = 0.f;
#pragma unroll
      for (int j = 0; j < 8; j++) { float pj = __expf(s[i][j] - m_new); s[i][j] = pj; rs += pj; }
      rs += __shfl_xor_sync(0xffffffffu, rs, 1);
      rs += __shfl_xor_sync(0xffffffffu, rs, 2);
      rs += __shfl_xor_sync(0xffffffffu, rs, 4);
      rs += __shfl_xor_sync(0xffffffffu, rs, 8);
      l_i[i] = l_i[i]*alpha + rs;
      m_i[i] = m_new;
#pragma unroll
      for (int j = 0; j < 4; j++) o[i][j] *= alpha;
      *(float4*)&Ps[(ty*8+i)*PS_LD + tx*8]     = make_float4(s[i][0], s[i][1], s[i][2], s[i][3]);
      *(float4*)&Ps[(ty*8+i)*PS_LD + tx*8 + 4] = make_float4(s[i][4], s[i][5], s[i][6], s[i][7]);
    }
    __syncthreads();

#pragma unroll 4
    for (int cc = 0; cc < 128; cc += 4) {
      float pv[8][4];
#pragma unroll
      for (int i = 0; i < 8; i++)
        *(float4*)&pv[i][0] = *(const float4*)&Ps[(ty*8+i)*PS_LD + cc];
      float vv[4][4];
#pragma unroll
      for (int mq = 0; mq < 4; mq++)
        *(float4*)&vv[mq][0] = *(const float4*)&Vs[(cc+mq)*VS_LD + tx*4];
#pragma unroll
      for (int i = 0; i < 8; i++)
#pragma unroll
        for (int mq = 0; mq < 4; mq++)
#pragma unroll
          for (int j = 0; j < 4; j++)
            o[i][j] = fmaf(pv[i][mq], vv[mq][j], o[i][j]);
    }
  }

  const int b = bh >> 4, h = bh & 15;
#pragma unroll
  for (int i = 0; i < 8; i++) {
    int row = q0 + ty*8 + i;
    float inv = 1.0f / l_i[i];
    size_t off = ((size_t)(b*SEQ + row))*CDIM + h*HDIM + tx*4;
    *(float4*)&g_y[off] = make_float4(o[i][0]*inv, o[i][1]*inv, o[i][2]*inv, o[i][3]*inv);
  }
}

// ---------------- launch ----------------
extern "C" void kernel_launch(void* const* d_in, const int* in_sizes, int n_in,
                              void* d_out, int out_size) {
  const float* x    = (const float*)d_in[0];
  const float* Wqkv = (const float*)d_in[1];
  const float* Wout = (const float*)d_in[2];
  float* out = (float*)d_out;

  float *qkv = nullptr, *y = nullptr;
  __nv_bfloat16 *Ahi=nullptr,*Alo=nullptr,*Bhi=nullptr,*Blo=nullptr;
  cudaGetSymbolAddress((void**)&qkv, g_qkv);
  cudaGetSymbolAddress((void**)&y,   g_y);
  cudaGetSymbolAddress((void**)&Ahi, g_Ahi);
  cudaGetSymbolAddress((void**)&Alo, g_Alo);
  cudaGetSymbolAddress((void**)&Bhi, g_Bhi);
  cudaGetSymbolAddress((void**)&Blo, g_Blo);

  cudaFuncSetAttribute(flash_attn_kernel,
                       cudaFuncAttributeMaxDynamicSharedMemorySize, ATT_SMEM_BYTES);
  cudaFuncSetAttribute(gemm_bf16x3,
                       cudaFuncAttributeMaxDynamicSharedMemorySize, GSM_TOTAL);

  rope_cache_kernel<<<(SEQ*HDIM + 255)/256, 256>>>();
  // qkv projection
  conv_split_kernel<<<(MROWS*CDIM/4 + 255)/256, 256>>>(x, Ahi, Alo, MROWS*CDIM);
  conv_split_kernel<<<(3*CDIM*CDIM/4 + 255)/256, 256>>>(Wqkv, Bhi, Blo, 3*CDIM*CDIM);
  gemm_bf16x3<<<dim3(3*CDIM/128, MROWS/128), 256, GSM_TOTAL>>>(Ahi, Alo, Bhi, Blo, qkv,
                                                               MROWS, 3*CDIM, CDIM);
  rope_apply_kernel<<<(MROWS*1536 + 255)/256, 256>>>();
  flash_attn_kernel<<<dim3(SEQ/128, BATCH*NHEAD), 256, ATT_SMEM_BYTES>>>();
  // output projection
  conv_split_kernel<<<(MROWS*CDIM/4 + 255)/256, 256>>>(y, Ahi, Alo, MROWS*CDIM);
  conv_split_kernel<<<(CDIM*CDIM/4 + 255)/256, 256>>>(Wout, Bhi, Blo, CDIM*CDIM);
  gemm_bf16x3<<<dim3(CDIM/128, MROWS/128), 256, GSM_TOTAL>>>(Ahi, Alo, Bhi, Blo, out,
                                                             MROWS, CDIM, CDIM);
}

// round 8
// speedup vs baseline: 2.6805x; 1.9153x over previous
#include <cuda_runtime.h>
#include <cuda_bf16.h>
#include <math_constants.h>
#include <cstdint>

#define NHEAD 16
#define HDIM  64
#define SEQ   2048
#define BATCH 2
#define CDIM  1024
#define MROWS (BATCH*SEQ)   // 4096
#define BHN   (BATCH*NHEAD) // 32

// ---------------- scratch ----------------
__device__ float g_qkv[(size_t)MROWS * 3 * CDIM];
__device__ float g_cos[SEQ*HDIM];
__device__ float g_sin[SEQ*HDIM];
// bf16 hi/lo split arrays
__device__ __align__(256) __nv_bfloat16 g_Qh[(size_t)BHN*SEQ*HDIM];
__device__ __align__(256) __nv_bfloat16 g_Ql[(size_t)BHN*SEQ*HDIM];
__device__ __align__(256) __nv_bfloat16 g_Kh[(size_t)BHN*SEQ*HDIM];
__device__ __align__(256) __nv_bfloat16 g_Kl[(size_t)BHN*SEQ*HDIM];
__device__ __align__(256) __nv_bfloat16 g_Vh[(size_t)BHN*SEQ*HDIM];
__device__ __align__(256) __nv_bfloat16 g_Vl[(size_t)BHN*SEQ*HDIM];
// GEMM staging (A reused: x for gemm1, attention O for gemm2)
__device__ __align__(256) __nv_bfloat16 g_Ahi[(size_t)MROWS*CDIM];
__device__ __align__(256) __nv_bfloat16 g_Alo[(size_t)MROWS*CDIM];
__device__ __align__(256) __nv_bfloat16 g_Bhi[(size_t)3*CDIM*CDIM];
__device__ __align__(256) __nv_bfloat16 g_Blo[(size_t)3*CDIM*CDIM];

static __device__ __forceinline__ uint32_t smem_u32(const void* p) {
  uint32_t a;
  asm("{ .reg .u64 t; cvta.to.shared.u64 t, %1; cvt.u32.u64 %0, t; }" : "=r"(a) : "l"(p));
  return a;
}
// pack (even,odd) floats into bf16x2 reg (lo half = even = smaller k index)
static __device__ __forceinline__ uint32_t packbf2(float even, float odd) {
  uint32_t r;
  asm("cvt.rn.bf16x2.f32 %0, %1, %2;" : "=r"(r) : "f"(odd), "f"(even));
  return r;
}
static __device__ __forceinline__ uint32_t packresid(uint32_t hi, float even, float odd) {
  float e = __uint_as_float(hi << 16);
  float o = __uint_as_float(hi & 0xFFFF0000u);
  return packbf2(even - e, odd - o);
}

// ---------------- RoPE cos/sin cache ----------------
__global__ void rope_cache_kernel() {
  int idx = blockIdx.x*blockDim.x + threadIdx.x;
  if (idx >= SEQ*HDIM) return;
  int t = idx >> 6;
  int d = idx & 63;
  int j = d & 31;
  float inv = powf(10000.0f, -(float)j / 32.0f);
  float ang = (float)t * inv;
  float s, c;
  sincosf(ang, &s, &c);
  g_cos[idx] = c;
  g_sin[idx] = s;
}

// ---------------- fp32 -> bf16 hi/lo split ----------------
__global__ void conv_split_kernel(const float* __restrict__ src,
                                  __nv_bfloat16* __restrict__ hi,
                                  __nv_bfloat16* __restrict__ lo, int n) {
  int i = (blockIdx.x*blockDim.x + threadIdx.x) * 4;
  if (i >= n) return;
  float4 v = *(const float4*)(src + i);
  __nv_bfloat16 h0 = __float2bfloat16(v.x);
  __nv_bfloat16 h1 = __float2bfloat16(v.y);
  __nv_bfloat16 h2 = __float2bfloat16(v.z);
  __nv_bfloat16 h3 = __float2bfloat16(v.w);
  __nv_bfloat16 l0 = __float2bfloat16(v.x - __bfloat162float(h0));
  __nv_bfloat16 l1 = __float2bfloat16(v.y - __bfloat162float(h1));
  __nv_bfloat16 l2 = __float2bfloat16(v.z - __bfloat162float(h2));
  __nv_bfloat16 l3 = __float2bfloat16(v.w - __bfloat162float(h3));
  __nv_bfloat162* hp = (__nv_bfloat162*)(hi + i);
  __nv_bfloat162* lp = (__nv_bfloat162*)(lo + i);
  hp[0] = __nv_bfloat162(h0, h1); hp[1] = __nv_bfloat162(h2, h3);
  lp[0] = __nv_bfloat162(l0, l1); lp[1] = __nv_bfloat162(l2, l3);
}

// ================= mma macros =================
#define LDSM4(R,ADDR) \
  asm volatile("ldmatrix.sync.aligned.m8n8.x4.shared.b16 {%0,%1,%2,%3}, [%4];" \
    : "=r"((R)[0]),"=r"((R)[1]),"=r"((R)[2]),"=r"((R)[3]) : "r"(ADDR))
#define LDSM4T(R,ADDR) \
  asm volatile("ldmatrix.sync.aligned.m8n8.x4.trans.shared.b16 {%0,%1,%2,%3}, [%4];" \
    : "=r"((R)[0]),"=r"((R)[1]),"=r"((R)[2]),"=r"((R)[3]) : "r"(ADDR))
#define MMA16816(D,A,B) \
  asm volatile("mma.sync.aligned.m16n8k16.row.col.f32.bf16.bf16.f32 " \
    "{%0,%1,%2,%3}, {%4,%5,%6,%7}, {%8,%9}, {%0,%1,%2,%3};" \
    : "+f"((D)[0]),"+f"((D)[1]),"+f"((D)[2]),"+f"((D)[3]) \
    : "r"((A)[0]),"r"((A)[1]),"r"((A)[2]),"r"((A)[3]), "r"((B)[0]),"r"((B)[1]))
#define CPASYNC16(DST,SRC) \
  asm volatile("cp.async.cg.shared.global [%0], [%1], 16;" :: "r"(DST), "l"(SRC) : "memory")

// ================= 3xBF16 mma.sync GEMM: C[M,N] = A[M,K] * B[N,K]^T (proven R5) =================
#define GP 40
#define COMP_BYTES (128*GP*2)
#define STAGE_BYTES (4*COMP_BYTES)
#define GSM_TOTAL (2*STAGE_BYTES)

__global__ __launch_bounds__(256, 2)
void gemm_bf16x3(const __nv_bfloat16* __restrict__ Ahi, const __nv_bfloat16* __restrict__ Alo,
                 const __nv_bfloat16* __restrict__ Bhi, const __nv_bfloat16* __restrict__ Blo,
                 float* __restrict__ C, int M, int N, int K) {
  extern __shared__ char sm[];
  const uint32_t sb = smem_u32(sm);
  const int tid = threadIdx.x, warp = tid >> 5, lane = tid & 31;
  const int m0 = blockIdx.y * 128, n0 = blockIdx.x * 128;
  const int warp_m = (warp >> 1) * 32, warp_n = (warp & 1) * 64;

  float acc[2][8][4];
#pragma unroll
  for (int f = 0; f < 2; f++)
#pragma unroll
    for (int t = 0; t < 8; t++)
#pragma unroll
      for (int j = 0; j < 4; j++) acc[f][t][j] = 0.f;

  const __nv_bfloat16* srcs[4] = {Ahi, Alo, Bhi, Blo};
  auto load_stage = [&](int stage, int k0) {
#pragma unroll
    for (int i = 0; i < 8; i++) {
      int t = tid + i * 256;
      int comp = t >> 9, row = (t >> 2) & 127, ch = t & 3;
      const __nv_bfloat16* src = srcs[comp] +
        (size_t)((comp < 2 ? m0 : n0) + row) * K + k0 + ch * 8;
      uint32_t dst = sb + stage * STAGE_BYTES + comp * COMP_BYTES + row * (GP*2) + ch * 16;
      CPASYNC16(dst, src);
    }
    asm volatile("cp.async.commit_group;" ::: "memory");
  };

  const int NIT = K / 32;
  load_stage(0, 0);
  for (int kt = 0; kt < NIT; kt++) {
    if (kt + 1 < NIT) {
      load_stage((kt + 1) & 1, (kt + 1) * 32);
      asm volatile("cp.async.wait_group 1;" ::: "memory");
    } else {
      asm volatile("cp.async.wait_group 0;" ::: "memory");
    }
    __syncthreads();
    const uint32_t base = sb + (kt & 1) * STAGE_BYTES;
#pragma unroll
    for (int ks = 0; ks < 2; ks++) {
      uint32_t ah[2][4], al[2][4];
      {
        int arow = (lane & 7) + ((lane >> 3) & 1) * 8;
        int akof = ks * 16 + ((lane >> 4) & 1) * 8;
#pragma unroll
        for (int f = 0; f < 2; f++) {
          uint32_t ao = base + (warp_m + f * 16 + arow) * (GP*2) + akof * 2;
          LDSM4(ah[f], ao);
          LDSM4(al[f], ao + COMP_BYTES);
        }
      }
      int brow = (lane & 7) + ((lane >> 4) & 1) * 8;
      int bkof = ks * 16 + ((lane >> 3) & 1) * 8;
#pragma unroll
      for (int p = 0; p < 4; p++) {
        uint32_t bo = base + 2 * COMP_BYTES + (warp_n + p * 16 + brow) * (GP*2) + bkof * 2;
        uint32_t bh[4], bl[4];
        LDSM4(bh, bo);
        LDSM4(bl, bo + COMP_BYTES);
#pragma unroll
        for (int half = 0; half < 2; half++) {
          int t = p * 2 + half;
          uint32_t* bhp = bh + half * 2;
          uint32_t* blp = bl + half * 2;
#pragma unroll
          for (int f = 0; f < 2; f++) {
            MMA16816(acc[f][t], ah[f], bhp);
            MMA16816(acc[f][t], ah[f], blp);
            MMA16816(acc[f][t], al[f], bhp);
          }
        }
      }
    }
    __syncthreads();
  }
  const int g = lane >> 2, tig = lane & 3;
#pragma unroll
  for (int f = 0; f < 2; f++) {
#pragma unroll
    for (int t = 0; t < 8; t++) {
      int row = m0 + warp_m + f * 16 + g;
      int col = n0 + warp_n + t * 8 + tig * 2;
      *(float2*)&C[(size_t)row * N + col]       = make_float2(acc[f][t][0], acc[f][t][1]);
      *(float2*)&C[(size_t)(row + 8) * N + col] = make_float2(acc[f][t][2], acc[f][t][3]);
    }
  }
}

// ---------------- RoPE apply + split to bf16 hi/lo, head-major ----------------
__global__ void rope_apply_kernel() {
  int p = blockIdx.x*blockDim.x + threadIdx.x;   // pair index
  if (p >= MROWS*1536) return;
  int m   = p / 1536;
  int col = (p % 1536) * 2;
  int b = m >> 11;
  int t = m & 2047;
  int sec = col >> 10;         // 0=q,1=k,2=v
  int cc  = col & 1023;
  int h = cc >> 6;
  int d = cc & 63;
  float2 v = *(const float2*)&g_qkv[(size_t)m*3072 + col];
  float r0, r1;
  if (sec < 2) {
    float c0 = g_cos[t*64 + d],     s0 = g_sin[t*64 + d];
    float c1 = g_cos[t*64 + d + 1], s1 = g_sin[t*64 + d + 1];
    r0 = v.x*c0 - v.y*s0;
    r1 = v.y*c1 + v.x*s1;
  } else { r0 = v.x; r1 = v.y; }
  if (sec == 0) { r0 *= 0.125f; r1 *= 0.125f; }   // fold 1/sqrt(64) into Q
  __nv_bfloat16 h0 = __float2bfloat16(r0), h1 = __float2bfloat16(r1);
  __nv_bfloat16 l0 = __float2bfloat16(r0 - __bfloat162float(h0));
  __nv_bfloat16 l1 = __float2bfloat16(r1 - __bfloat162float(h1));
  __nv_bfloat16 *dh = (sec == 0) ? g_Qh : (sec == 1) ? g_Kh : g_Vh;
  __nv_bfloat16 *dl = (sec == 0) ? g_Ql : (sec == 1) ? g_Kl : g_Vl;
  size_t o = ((size_t)((b*NHEAD + h)*SEQ + t))*HDIM + d;
  *(__nv_bfloat162*)&dh[o] = __nv_bfloat162(h0, h1);
  *(__nv_bfloat162*)&dl[o] = __nv_bfloat162(l0, l1);
}

// ================= tensor-core flash attention (3xBF16 both GEMMs) =================
// 256 thr / 8 warps; warp w owns q rows [q0+16w, +16). 128-key tiles, double-buffered.
// smem areas (pitch 144B, 128 rows): 0=Qh 1=Ql, buf b: 2+4b+{Kh,Kl,Vh,Vl}
#define AP_B   144
#define AREA_B (128*AP_B)          // 18432
#define ATT2_SMEM (10*AREA_B)      // 184320

__global__ __launch_bounds__(256, 1)
void flash_attn_tc() {
  extern __shared__ char smb[];
  const uint32_t sb = smem_u32(smb);
  const int tid = threadIdx.x, w = tid >> 5, lane = tid & 31;
  const int g = lane >> 2, tig = lane & 3;
  const int q0 = blockIdx.x * 128;
  const int bh = blockIdx.y;
  const size_t base = (size_t)bh * SEQ * HDIM;
  const __nv_bfloat16* kvsrc[4] = { g_Kh + base, g_Kl + base, g_Vh + base, g_Vl + base };

  auto stage_kv = [&](int kt, int buf) {
#pragma unroll
    for (int i = 0; i < 16; i++) {
      int t = tid + i * 256;
      int comp = t >> 10, r = (t >> 3) & 127, ch = t & 7;
      const void* src = kvsrc[comp] + (size_t)(kt * 128 + r) * 64 + ch * 8;
      uint32_t dst = sb + (2 + 4 * buf + comp) * AREA_B + r * AP_B + ch * 16;
      CPASYNC16(dst, src);
    }
    asm volatile("cp.async.commit_group;" ::: "memory");
  };

  // stage Q (group 0) + KV tile 0 (group 1)
  {
    const __nv_bfloat16* qs[2] = { g_Qh + base, g_Ql + base };
#pragma unroll
    for (int i = 0; i < 8; i++) {
      int t = tid + i * 256;
      int comp = t >> 10, r = (t >> 3) & 127, ch = t & 7;
      const void* src = qs[comp] + (size_t)(q0 + r) * 64 + ch * 8;
      uint32_t dst = sb + comp * AREA_B + r * AP_B + ch * 16;
      CPASYNC16(dst, src);
    }
    asm volatile("cp.async.commit_group;" ::: "memory");
  }
  stage_kv(0, 0);
  asm volatile("cp.async.wait_group 1;" ::: "memory");  // Q ready
  __syncthreads();

  // Q fragments -> registers (A m16k16 per kstep, hi+lo)
  uint32_t qh[4][4], ql[4][4];
#pragma unroll
  for (int ks = 0; ks < 4; ks++) {
    uint32_t ro = (uint32_t)((w * 16 + (lane & 7) + ((lane >> 3) & 1) * 8) * AP_B
                           + (ks * 16 + ((lane >> 4) & 1) * 8) * 2);
    LDSM4(qh[ks], sb + ro);
    LDSM4(ql[ks], sb + AREA_B + ro);
  }

  float m0 = -CUDART_INF_F, m1 = -CUDART_INF_F, l0 = 0.f, l1 = 0.f;
  float o[8][4];
#pragma unroll
  for (int t = 0; t < 8; t++)
#pragma unroll
    for (int j = 0; j < 4; j++) o[t][j] = 0.f;

  for (int kt = 0; kt < SEQ/128; kt++) {
    if (kt + 1 < SEQ/128) {
      stage_kv(kt + 1, (kt + 1) & 1);
      asm volatile("cp.async.wait_group 1;" ::: "memory");
    } else {
      asm volatile("cp.async.wait_group 0;" ::: "memory");
    }
    __syncthreads();
    const uint32_t kb = sb + (2 + 4 * (kt & 1)) * AREA_B;  // Kh; +AREA_B=Kl; +2*=Vh; +3*=Vl

    // ---- S = Q @ K^T (3 terms) ----
    float s[16][4];
#pragma unroll
    for (int nt = 0; nt < 16; nt++)
#pragma unroll
      for (int j = 0; j < 4; j++) s[nt][j] = 0.f;
#pragma unroll
    for (int ks = 0; ks < 4; ks++) {
#pragma unroll
      for (int jj = 0; jj < 8; jj++) {
        uint32_t ro = (uint32_t)((jj * 16 + (lane & 7) + ((lane >> 4) & 1) * 8) * AP_B
                               + (ks * 16 + ((lane >> 3) & 1) * 8) * 2);
        uint32_t bh4[4], bl4[4];
        LDSM4(bh4, kb + ro);
        LDSM4(bl4, kb + AREA_B + ro);
        MMA16816(s[2*jj],   qh[ks], bh4);
        MMA16816(s[2*jj],   qh[ks], bl4);
        MMA16816(s[2*jj],   ql[ks], bh4);
        MMA16816(s[2*jj+1], qh[ks], bh4 + 2);
        MMA16816(s[2*jj+1], qh[ks], bl4 + 2);
        MMA16816(s[2*jj+1], ql[ks], bh4 + 2);
      }
    }

    // ---- online softmax (rows g and g+8) ----
    float mx0 = s[0][0], mx1 = s[0][2];
#pragma unroll
    for (int nt = 0; nt < 16; nt++) {
      mx0 = fmaxf(mx0, fmaxf(s[nt][0], s[nt][1]));
      mx1 = fmaxf(mx1, fmaxf(s[nt][2], s[nt][3]));
    }
    mx0 = fmaxf(mx0, __shfl_xor_sync(0xffffffffu, mx0, 1));
    mx0 = fmaxf(mx0, __shfl_xor_sync(0xffffffffu, mx0, 2));
    mx1 = fmaxf(mx1, __shfl_xor_sync(0xffffffffu, mx1, 1));
    mx1 = fmaxf(mx1, __shfl_xor_sync(0xffffffffu, mx1, 2));
    float mn0 = fmaxf(m0, mx0), mn1 = fmaxf(m1, mx1);
    float a0 = __expf(m0 - mn0), a1 = __expf(m1 - mn1);
    float rs0 = 0.f, rs1 = 0.f;
#pragma unroll
    for (int nt = 0; nt < 16; nt++) {
      s[nt][0] = __expf(s[nt][0] - mn0); rs0 += s[nt][0];
      s[nt][1] = __expf(s[nt][1] - mn0); rs0 += s[nt][1];
      s[nt][2] = __expf(s[nt][2] - mn1); rs1 += s[nt][2];
      s[nt][3] = __expf(s[nt][3] - mn1); rs1 += s[nt][3];
    }
    rs0 += __shfl_xor_sync(0xffffffffu, rs0, 1);
    rs0 += __shfl_xor_sync(0xffffffffu, rs0, 2);
    rs1 += __shfl_xor_sync(0xffffffffu, rs1, 1);
    rs1 += __shfl_xor_sync(0xffffffffu, rs1, 2);
    l0 = l0 * a0 + rs0; l1 = l1 * a1 + rs1;
    m0 = mn0; m1 = mn1;
#pragma unroll
    for (int t = 0; t < 8; t++) {
      o[t][0] *= a0; o[t][1] *= a0; o[t][2] *= a1; o[t][3] *= a1;
    }

    // ---- O += P @ V (3 terms); P from registers via C->A fragment identity ----
#pragma unroll
    for (int J = 0; J < 8; J++) {
      uint32_t pah[4], pal[4];
      pah[0] = packbf2(s[2*J][0],   s[2*J][1]);
      pah[1] = packbf2(s[2*J][2],   s[2*J][3]);
      pah[2] = packbf2(s[2*J+1][0], s[2*J+1][1]);
      pah[3] = packbf2(s[2*J+1][2], s[2*J+1][3]);
      pal[0] = packresid(pah[0], s[2*J][0],   s[2*J][1]);
      pal[1] = packresid(pah[1], s[2*J][2],   s[2*J][3]);
      pal[2] = packresid(pah[2], s[2*J+1][0], s[2*J+1][1]);
      pal[3] = packresid(pah[3], s[2*J+1][2], s[2*J+1][3]);
#pragma unroll
      for (int tt = 0; tt < 4; tt++) {
        uint32_t ro = (uint32_t)((J * 16 + (lane & 7) + ((lane >> 3) & 1) * 8) * AP_B
                               + (tt * 16 + ((lane >> 4) & 1) * 8) * 2);
        uint32_t vh4[4], vl4[4];
        LDSM4T(vh4, kb + 2 * AREA_B + ro);
        LDSM4T(vl4, kb + 3 * AREA_B + ro);
        MMA16816(o[2*tt],   pah, vh4);
        MMA16816(o[2*tt],   pah, vl4);
        MMA16816(o[2*tt],   pal, vh4);
        MMA16816(o[2*tt+1], pah, vh4 + 2);
        MMA16816(o[2*tt+1], pah, vl4 + 2);
        MMA16816(o[2*tt+1], pal, vh4 + 2);
      }
    }
    __syncthreads();   // all warps done reading this KV buffer
  }

  // ---- epilogue: normalize + split write into gemm2 A staging ----
  const float i0 = 1.f / l0, i1 = 1.f / l1;
  const int b = bh >> 4, h = bh & 15;
  const int r0 = q0 + w * 16 + g, r1 = r0 + 8;
  const size_t ro0 = (size_t)(b * SEQ + r0) * CDIM + h * 64;
  const size_t ro1 = (size_t)(b * SEQ + r1) * CDIM + h * 64;
#pragma unroll
  for (int t = 0; t < 8; t++) {
    int col = t * 8 + tig * 2;
    float f0 = o[t][0] * i0, f1 = o[t][1] * i0;
    float f2 = o[t][2] * i1, f3 = o[t][3] * i1;
    uint32_t h0 = packbf2(f0, f1), h1 = packbf2(f2, f3);
    *(uint32_t*)&g_Ahi[ro0 + col] = h0;
    *(uint32_t*)&g_Alo[ro0 + col] = packresid(h0, f0, f1);
    *(uint32_t*)&g_Ahi[ro1 + col] = h1;
    *(uint32_t*)&g_Alo[ro1 + col] = packresid(h1, f2, f3);
  }
}

// ---------------- launch ----------------
extern "C" void kernel_launch(void* const* d_in, const int* in_sizes, int n_in,
                              void* d_out, int out_size) {
  const float* x    = (const float*)d_in[0];
  const float* Wqkv = (const float*)d_in[1];
  const float* Wout = (const float*)d_in[2];
  float* out = (float*)d_out;

  float *qkv = nullptr;
  __nv_bfloat16 *Ahi=nullptr,*Alo=nullptr,*Bhi=nullptr,*Blo=nullptr;
  cudaGetSymbolAddress((void**)&qkv, g_qkv);
  cudaGetSymbolAddress((void**)&Ahi, g_Ahi);
  cudaGetSymbolAddress((void**)&Alo, g_Alo);
  cudaGetSymbolAddress((void**)&Bhi, g_Bhi);
  cudaGetSymbolAddress((void**)&Blo, g_Blo);

  cudaFuncSetAttribute(gemm_bf16x3,
                       cudaFuncAttributeMaxDynamicSharedMemorySize, GSM_TOTAL);
  cudaFuncSetAttribute(flash_attn_tc,
                       cudaFuncAttributeMaxDynamicSharedMemorySize, ATT2_SMEM);

  rope_cache_kernel<<<(SEQ*HDIM + 255)/256, 256>>>();
  // qkv projection
  conv_split_kernel<<<(MROWS*CDIM/4 + 255)/256, 256>>>(x, Ahi, Alo, MROWS*CDIM);
  conv_split_kernel<<<(3*CDIM*CDIM/4 + 255)/256, 256>>>(Wqkv, Bhi, Blo, 3*CDIM*CDIM);
  gemm_bf16x3<<<dim3(3*CDIM/128, MROWS/128), 256, GSM_TOTAL>>>(Ahi, Alo, Bhi, Blo, qkv,
                                                               MROWS, 3*CDIM, CDIM);
  // RoPE + split
  rope_apply_kernel<<<(MROWS*1536 + 255)/256, 256>>>();
  // attention (writes g_Ahi/g_Alo directly)
  flash_attn_tc<<<dim3(SEQ/128, BHN), 256, ATT2_SMEM>>>();
  // output projection
  conv_split_kernel<<<(CDIM*CDIM/4 + 255)/256, 256>>>(Wout, Bhi, Blo, CDIM*CDIM);
  gemm_bf16x3<<<dim3(CDIM/128, MROWS/128), 256, GSM_TOTAL>>>(Ahi, Alo, Bhi, Blo, out,
                                                             MROWS, CDIM, CDIM);
}